// round 6
// baseline (speedup 1.0000x reference)
#include <cuda_runtime.h>

#define DB 2     // batch
#define DL 64    // L
#define DT 32    // T
#define DD 256   // D
#define NITEMS (DB * DL * DL)       // 8192 (bi, j) work items

// Scratch (device globals: no allocation allowed)
__device__ float  g_Qk[DB * DL * DD];     // per (b,i): ((q@Wq^T+bq)/16)@Wk
__device__ float  g_WcombT[DD * DD];      // WcombT[d,f] = sum_e Wv[e,d]*Wf[f,e]
__device__ float  g_bcomb[DD];            // bcomb[f] = sum_e Wf[f,e]*bv[e] + bf[f]
__device__ float4 g_vbar[NITEMS * 64];    // 8MB: per-item attn-weighted value
__device__ int    g_ticket;               // dynamic work ticket

// ---------------------------------------------------------------------------
// Single prologue kernel, block = (32,32) = 1024 threads.
// ---------------------------------------------------------------------------
__global__ void prologue_kernel(const float* __restrict__ query,
                                const float* __restrict__ Wq,
                                const float* __restrict__ bq,
                                const float* __restrict__ Wk,
                                const float* __restrict__ Wv,
                                const float* __restrict__ bv,
                                const float* __restrict__ Wf,
                                const float* __restrict__ bf) {
    const int tx = threadIdx.x, ty = threadIdx.y;
    const int tid = ty * 32 + tx;
    const int blk = blockIdx.x;

    if (blk < 64) {
        __shared__ float Av[2][32][33];   // Av[buf][k][m] = Wv[e0+k, d0+m]
        __shared__ float Bf[2][32][33];   // Bf[buf][m][k] = Wf[f0+m, e0+k]
        const int f0 = (blk & 7) * 32;
        const int d0 = (blk >> 3) * 32;

        Av[0][ty][tx] = Wv[(size_t)ty * DD + d0 + tx];
        Bf[0][ty][tx] = Wf[(size_t)(f0 + ty) * DD + tx];
        __syncthreads();

        float acc = 0.f;
#pragma unroll
        for (int s = 0; s < 8; s++) {
            const int cur = s & 1;
            if (s < 7) {
                const int e0 = (s + 1) * 32;
                Av[cur ^ 1][ty][tx] = Wv[(size_t)(e0 + ty) * DD + d0 + tx];
                Bf[cur ^ 1][ty][tx] = Wf[(size_t)(f0 + ty) * DD + e0 + tx];
            }
#pragma unroll
            for (int k = 0; k < 32; k++) acc += Av[cur][k][ty] * Bf[cur][tx][k];
            __syncthreads();
        }
        g_WcombT[(size_t)(d0 + ty) * DD + f0 + tx] = acc;

    } else if (blk < 192) {
        const int bi = blk - 64;
        __shared__ float q[DD];
        __shared__ float Qs[DD];
        __shared__ float part[4][DD];

        if (tid < DD) q[tid] = query[bi * DD + tid];
        __syncthreads();

#pragma unroll
        for (int i = 0; i < 8; i++) {
            const int e = ty * 8 + i;
            const float* wq = Wq + (size_t)e * DD;
            float p = 0.f;
#pragma unroll
            for (int c = 0; c < 8; c++) p += q[tx + 32 * c] * wq[tx + 32 * c];
#pragma unroll
            for (int off = 16; off; off >>= 1)
                p += __shfl_xor_sync(0xffffffffu, p, off);
            if (tx == 0) Qs[e] = (p + bq[e]) * 0.0625f;
        }
        __syncthreads();

        const int quarter = ty >> 3;
        const int d = tx + (ty & 7) * 32;
        const int e0 = quarter * 64;
        float acc = 0.f;
#pragma unroll 8
        for (int e = 0; e < 64; e++)
            acc += Qs[e0 + e] * Wk[(size_t)(e0 + e) * DD + d];
        part[quarter][d] = acc;
        __syncthreads();
        if (tid < DD)
            g_Qk[bi * DD + tid] = part[0][tid] + part[1][tid] + part[2][tid] + part[3][tid];

    } else {
        if (tid == 0) g_ticket = 0;
        __shared__ float bvs[DD];
        if (tid < DD) bvs[tid] = bv[tid];
        __syncthreads();
#pragma unroll
        for (int i = 0; i < 8; i++) {
            const int f = ty * 8 + i;
            const float* wf = Wf + (size_t)f * DD;
            float p = 0.f;
#pragma unroll
            for (int c = 0; c < 8; c++) p += bvs[tx + 32 * c] * wf[tx + 32 * c];
#pragma unroll
            for (int off = 16; off; off >>= 1)
                p += __shfl_xor_sync(0xffffffffu, p, off);
            if (tx == 0) g_bcomb[f] = p + bf[f];
        }
    }
}

// ---------------------------------------------------------------------------
// Phase-A helpers: eager binary-tree score fold (bit-reversed t order).
// ---------------------------------------------------------------------------
__device__ __forceinline__ float fold2(float x, float y, int o, int lane) {
    const bool hi = (lane & o) != 0;
    const float send = hi ? x : y;
    const float recv = __shfl_xor_sync(0xffffffffu, send, o);
    return (hi ? y : x) + recv;
}

__device__ __forceinline__ float score_pair(const float4* __restrict__ kp,
                                            int lane,
                                            const float4 qk0, const float4 qk1,
                                            int t) {
    const float4 a0 = __ldcs(kp + t * 64 + lane);
    const float4 a1 = __ldcs(kp + t * 64 + 32 + lane);
    const float4 b0 = __ldcs(kp + (t + 16) * 64 + lane);
    const float4 b1 = __ldcs(kp + (t + 16) * 64 + 32 + lane);
    const float sa = a0.x * qk0.x + a0.y * qk0.y + a0.z * qk0.z + a0.w * qk0.w
                   + a1.x * qk1.x + a1.y * qk1.y + a1.z * qk1.z + a1.w * qk1.w;
    const float sb = b0.x * qk0.x + b0.y * qk0.y + b0.z * qk0.z + b0.w * qk0.w
                   + b1.x * qk1.x + b1.y * qk1.y + b1.z * qk1.z + b1.w * qk1.w;
    return fold2(sa, sb, 16, lane);
}

// ---------------------------------------------------------------------------
// Main streaming kernel: NO smem, NO barriers. Each warp independently pulls
// (bi,j) items from a global ticket, streams key+value, writes vbar.
// grid = 740 persistent blocks (5/SM at 48 regs), block = 256.
// ---------------------------------------------------------------------------
__global__ __launch_bounds__(256, 5)
void attn_stream_kernel(const float4* __restrict__ key4,
                        const float4* __restrict__ value4) {
    const int lane = threadIdx.x & 31;

    for (;;) {
        int item;
        if (lane == 0) item = atomicAdd(&g_ticket, 1);
        item = __shfl_sync(0xffffffffu, item, 0);
        if (item >= NITEMS) return;

        const int bi = item >> 6;               // (b*L + i), 0..127

        const float4* qk4 = reinterpret_cast<const float4*>(g_Qk) + bi * 64;
        const float4 qk0 = qk4[lane];
        const float4 qk1 = qk4[32 + lane];

        const size_t base = (size_t)item * (DT * 64);   // float4 units
        const float4* kp = key4 + base;
        const float4* vp = value4 + base;

        // ---- Phase A: eager tree fold, few live score regs ----
        float h0, h1;
        {
            float m08 = fold2(score_pair(kp, lane, qk0, qk1, 0),
                              score_pair(kp, lane, qk0, qk1, 8), 8, lane);
            float m4  = fold2(score_pair(kp, lane, qk0, qk1, 4),
                              score_pair(kp, lane, qk0, qk1, 12), 8, lane);
            float q0  = fold2(m08, m4, 4, lane);
            float m2  = fold2(score_pair(kp, lane, qk0, qk1, 2),
                              score_pair(kp, lane, qk0, qk1, 10), 8, lane);
            float m6  = fold2(score_pair(kp, lane, qk0, qk1, 6),
                              score_pair(kp, lane, qk0, qk1, 14), 8, lane);
            float q1  = fold2(m2, m6, 4, lane);
            h0 = fold2(q0, q1, 2, lane);        // all even t
        }
        {
            float m1  = fold2(score_pair(kp, lane, qk0, qk1, 1),
                              score_pair(kp, lane, qk0, qk1, 9), 8, lane);
            float m5  = fold2(score_pair(kp, lane, qk0, qk1, 5),
                              score_pair(kp, lane, qk0, qk1, 13), 8, lane);
            float q2  = fold2(m1, m5, 4, lane);
            float m3  = fold2(score_pair(kp, lane, qk0, qk1, 3),
                              score_pair(kp, lane, qk0, qk1, 11), 8, lane);
            float m7  = fold2(score_pair(kp, lane, qk0, qk1, 7),
                              score_pair(kp, lane, qk0, qk1, 15), 8, lane);
            float q3  = fold2(m3, m7, 4, lane);
            h1 = fold2(q2, q3, 2, lane);        // all odd t
        }
        const float myscore = fold2(h0, h1, 1, lane);   // lane l = score[t=l]

        // ---- warp-local softmax over T=32 ----
        float m = myscore;
#pragma unroll
        for (int off = 16; off; off >>= 1)
            m = fmaxf(m, __shfl_xor_sync(0xffffffffu, m, off));
        const float ex = __expf(myscore - m);
        float ssum = ex;
#pragma unroll
        for (int off = 16; off; off >>= 1)
            ssum += __shfl_xor_sync(0xffffffffu, ssum, off);
        const float a = ex / ssum;              // attn[t = lane]

        // ---- Phase B: vbar[d] = sum_t attn[t] * value[t,d] ----
        float4 acc0 = make_float4(0.f, 0.f, 0.f, 0.f);
        float4 acc1 = make_float4(0.f, 0.f, 0.f, 0.f);
#pragma unroll
        for (int t = 0; t < DT; t++) {
            const float at = __shfl_sync(0xffffffffu, a, t);
            const float4 v0 = __ldcs(vp + t * 64 + lane);
            const float4 v1 = __ldcs(vp + t * 64 + 32 + lane);
            acc0.x += at * v0.x; acc0.y += at * v0.y;
            acc0.z += at * v0.z; acc0.w += at * v0.w;
            acc1.x += at * v1.x; acc1.y += at * v1.y;
            acc1.z += at * v1.z; acc1.w += at * v1.w;
        }
        float4* vb = g_vbar + (size_t)item * 64;
        vb[lane]      = acc0;
        vb[32 + lane] = acc1;
    }
}

// ---------------------------------------------------------------------------
// Epilogue GEMM: out[r, f] = sum_d vbar[r, d] * WcombT[d, f] + bcomb[f]
// r = 0..8191, classic 64x64 tile, thread 4x4, K-slabs of 16. L2-hot.
// grid = (128, 4), block = (16, 16)
// ---------------------------------------------------------------------------
__global__ __launch_bounds__(256)
void out_gemm_kernel(float* __restrict__ out) {
    __shared__ float As[64][17];
    __shared__ float Bs[16][65];
    const int tx = threadIdx.x, ty = threadIdx.y;
    const int tid = ty * 16 + tx;
    const int row0 = blockIdx.x * 64;
    const int f0   = blockIdx.y * 64;

    const int ar  = tid >> 2, ak4 = tid & 3;    // A loader: row, k-quarter
    const int bk  = tid >> 4, bf4 = tid & 15;   // B loader: k, f-quarter

    float acc[4][4];
#pragma unroll
    for (int i = 0; i < 4; i++)
#pragma unroll
        for (int jj = 0; jj < 4; jj++) acc[i][jj] = 0.f;

    for (int k0 = 0; k0 < DD; k0 += 16) {
        const float4 av = g_vbar[(size_t)(row0 + ar) * 64 + (k0 >> 2) + ak4];
        As[ar][ak4 * 4 + 0] = av.x;
        As[ar][ak4 * 4 + 1] = av.y;
        As[ar][ak4 * 4 + 2] = av.z;
        As[ar][ak4 * 4 + 3] = av.w;
        const float4 bvv = *reinterpret_cast<const float4*>(
            &g_WcombT[(size_t)(k0 + bk) * DD + f0 + bf4 * 4]);
        Bs[bk][bf4 * 4 + 0] = bvv.x;
        Bs[bk][bf4 * 4 + 1] = bvv.y;
        Bs[bk][bf4 * 4 + 2] = bvv.z;
        Bs[bk][bf4 * 4 + 3] = bvv.w;
        __syncthreads();

#pragma unroll
        for (int k = 0; k < 16; k++) {
            float arr[4], brr[4];
#pragma unroll
            for (int i = 0; i < 4; i++) arr[i] = As[ty * 4 + i][k];
#pragma unroll
            for (int jj = 0; jj < 4; jj++) brr[jj] = Bs[k][tx * 4 + jj];
#pragma unroll
            for (int i = 0; i < 4; i++)
#pragma unroll
                for (int jj = 0; jj < 4; jj++) acc[i][jj] += arr[i] * brr[jj];
        }
        __syncthreads();
    }

    const float bc0 = g_bcomb[f0 + tx * 4 + 0];
    const float bc1 = g_bcomb[f0 + tx * 4 + 1];
    const float bc2 = g_bcomb[f0 + tx * 4 + 2];
    const float bc3 = g_bcomb[f0 + tx * 4 + 3];
#pragma unroll
    for (int i = 0; i < 4; i++) {
        float4 o;
        o.x = acc[i][0] + bc0;
        o.y = acc[i][1] + bc1;
        o.z = acc[i][2] + bc2;
        o.w = acc[i][3] + bc3;
        *reinterpret_cast<float4*>(&out[(size_t)(row0 + ty * 4 + i) * DD + f0 + tx * 4]) = o;
    }
}

// ---------------------------------------------------------------------------
// Launch. Input order: key, value, query, Wk, bk, Wv, bv, Wq, bq, Wf, bf
// ---------------------------------------------------------------------------
extern "C" void kernel_launch(void* const* d_in, const int* in_sizes, int n_in,
                              void* d_out, int out_size) {
    const float* key   = (const float*)d_in[0];
    const float* value = (const float*)d_in[1];
    const float* query = (const float*)d_in[2];
    const float* Wk    = (const float*)d_in[3];
    // bk (d_in[4]) cancels under softmax — unused.
    const float* Wv    = (const float*)d_in[5];
    const float* bv    = (const float*)d_in[6];
    const float* Wq    = (const float*)d_in[7];
    const float* bq    = (const float*)d_in[8];
    const float* Wf    = (const float*)d_in[9];
    const float* bf    = (const float*)d_in[10];
    float* out = (float*)d_out;

    prologue_kernel<<<193, dim3(32, 32)>>>(query, Wq, bq, Wk, Wv, bv, Wf, bf);

    attn_stream_kernel<<<740, 256>>>(
        reinterpret_cast<const float4*>(key),
        reinterpret_cast<const float4*>(value));

    out_gemm_kernel<<<dim3(128, 4), dim3(16, 16)>>>(out);
}